// round 9
// baseline (speedup 1.0000x reference)
#include <cuda_runtime.h>

#define BATCH 1024
#define T     336
#define PRED  96
#define D     64
#define HD    64
#define G     256
#define NROWS (BATCH * T)

typedef unsigned long long ull;

// Scratch (device globals: allocation-free per harness rules)
__device__ float g_p[(size_t)BATCH * T * G];       // gate pre-acts (352 MB)
__device__ float g_h1[(size_t)BATCH * T * HD];     // layer-0 hidden states (88 MB)
__device__ float g_h2last[BATCH * HD];

// Packed fp32x2 FMA (Blackwell — PTX-only)
#define FMA2(acc, a, b) \
    asm("fma.rn.f32x2 %0, %1, %2, %0;" : "+l"(acc) : "l"(a), "l"(b))
#define UNPACK2(lo, hi, v) \
    asm("mov.b64 {%0, %1}, %2;" : "=f"(lo), "=f"(hi) : "l"(v))

// HW tanh unit: 1 MUFU
__device__ __forceinline__ float fast_tanh(float x) {
    float y;
    asm("tanh.approx.f32 %0, %1;" : "=f"(y) : "f"(x));
    return y;
}
__device__ __forceinline__ float fast_sigmoid(float x) {
    return fmaf(fast_tanh(0.5f * x), 0.5f, 0.5f);
}

// ---------------------------------------------------------------------------
// Input GEMM (persistent, 256 thr, 2 CTAs/SM): 16-row tiles. (R8, unchanged)
// ---------------------------------------------------------------------------
__global__ void __launch_bounds__(256, 2) input_gemm(
    const float* __restrict__ In,   // [N, 64]
    const float* __restrict__ W,    // [256, 64]
    const float* __restrict__ b1,
    const float* __restrict__ b2,
    float* __restrict__ P,          // [N, 256]
    int N)
{
    __shared__ __align__(16) float sX[2][16 * 64];

    const int tid = threadIdx.x;
    const int g   = tid;

    ull w[32];
    {
        const ull* wp = (const ull*)(W + g * 64);
        #pragma unroll
        for (int i = 0; i < 32; i++) w[i] = wp[i];
    }
    const float bias = b1[g] + b2[g];

    const int ntiles = N / 16;
    const int stride = gridDim.x;
    int tile = blockIdx.x;
    if (tile >= ntiles) return;

    float4 xr = *(const float4*)(In + (size_t)tile * (16 * 64) + tid * 4);
    *(float4*)&sX[0][tid * 4] = xr;
    __syncthreads();

    int buf = 0;
    for (; tile < ntiles; tile += stride) {
        const int nxt = tile + stride;
        if (nxt < ntiles)
            xr = *(const float4*)(In + (size_t)nxt * (16 * 64) + tid * 4);

        ull acc[16];
        #pragma unroll
        for (int r = 0; r < 16; r++) acc[r] = 0ull;

        const float* xb = sX[buf];
        #pragma unroll
        for (int kg = 0; kg < 16; kg++) {
            ull w01 = w[2 * kg], w23 = w[2 * kg + 1];
            #pragma unroll
            for (int r = 0; r < 16; r++) {
                ulonglong2 xv = *(const ulonglong2*)&xb[r * 64 + kg * 4];
                FMA2(acc[r], w01, xv.x);
                FMA2(acc[r], w23, xv.y);
            }
        }

        if (nxt < ntiles)
            *(float4*)&sX[buf ^ 1][tid * 4] = xr;

        float* prow = P + (size_t)tile * 16 * G + g;
        #pragma unroll
        for (int r = 0; r < 16; r++) {
            float lo, hi;
            UNPACK2(lo, hi, acc[r]);
            __stcs(&prow[(size_t)r * G], lo + hi + bias);
        }
        __syncthreads();
        buf ^= 1;
    }
}

// ---------------------------------------------------------------------------
// Recurrent scan v4 (gate-pair threads): 256 thr, BT=8, grid=128, 1 CTA/SM.
// Thread owns gate rows (gA=pair, gB=pair+128) and row-half rh -> each hv
// LDS.128 feeds 4 FMA2 (ratio 4:1 vs 2:1). Cell: thread (eb,ej) owns rows
// eb and eb+4 with two register c's. 2 barriers/step.
// ---------------------------------------------------------------------------
template <bool WRITE_ALL>
__global__ void __launch_bounds__(256, 1) lstm_recur(
    const float* __restrict__ P,     // [BATCH, T, 256] (biases included)
    const float* __restrict__ Whh,   // [256, 64]
    float* __restrict__ hout)        // WRITE_ALL ? [BATCH,T,64] : [BATCH,64]
{
    __shared__ __align__(16) float sH[8 * 64];
    __shared__ __align__(16) float sGate[8 * G];

    const int tid  = threadIdx.x;
    const int pair = tid & 127;          // gate pair index
    const int rh   = tid >> 7;           // row-half: rows [rh*4, rh*4+4)
    const int gA   = pair;               // gates 0..127  (i,f -> sigmoid)
    const int gB   = pair + 128;         // gates 128..255 (g,o)
    const int b0   = blockIdx.x * 8;

    ull wA[32], wB[32];
    {
        const ull* wa = (const ull*)(Whh + gA * 64);
        const ull* wb = (const ull*)(Whh + gB * 64);
        #pragma unroll
        for (int i = 0; i < 32; i++) { wA[i] = wa[i]; wB[i] = wb[i]; }
    }
    // gB activation: tanh for pair<64 (g gate), sigmoid otherwise (o gate)
    const bool  gB_tanh = (pair < 64);
    const float taB = gB_tanh ? 1.0f : 0.5f;
    const float s1B = gB_tanh ? 1.0f : 0.5f;
    const float s2B = gB_tanh ? 0.0f : 0.5f;

    // cell-update identity: rows eb and eb+4, column ej
    const int eb = tid >> 6;             // 0..3
    const int ej = tid & 63;
    float c0 = 0.0f, c1 = 0.0f;

    sH[tid] = 0.0f;
    sH[tid + 256] = 0.0f;

    // P pointers: batch rows (b0 + rh*4 + b), gate columns gA / gB(=gA+128)
    const float* pbase = P + ((size_t)(b0 + rh * 4) * T) * G + gA;
    float pcA[4], pcB[4];
    #pragma unroll
    for (int b = 0; b < 4; b++) {
        pcA[b] = pbase[(size_t)b * T * G];
        pcB[b] = pbase[(size_t)b * T * G + 128];
    }
    __syncthreads();

    for (int t = 0; t < T; t++) {
        float pnA[4], pnB[4];
        if (t + 1 < T) {
            #pragma unroll
            for (int b = 0; b < 4; b++) {
                const float* pt = pbase + (size_t)b * T * G + (size_t)(t + 1) * G;
                pnA[b] = __ldcs(pt);
                pnB[b] = __ldcs(pt + 128);
            }
        }

        ull accA[4], accB[4];
        #pragma unroll
        for (int b = 0; b < 4; b++) { accA[b] = 0ull; accB[b] = 0ull; }

        #pragma unroll
        for (int kg = 0; kg < 16; kg++) {
            ull a01 = wA[2 * kg], a23 = wA[2 * kg + 1];
            ull b01 = wB[2 * kg], b23 = wB[2 * kg + 1];
            #pragma unroll
            for (int b = 0; b < 4; b++) {
                ulonglong2 hv = *(const ulonglong2*)&sH[(rh * 4 + b) * 64 + kg * 4];
                FMA2(accA[b], a01, hv.x);
                FMA2(accA[b], a23, hv.y);
                FMA2(accB[b], b01, hv.x);
                FMA2(accB[b], b23, hv.y);
            }
        }

        #pragma unroll
        for (int b = 0; b < 4; b++) {
            float lo, hi;
            UNPACK2(lo, hi, accA[b]);
            float vA = lo + hi + pcA[b];
            sGate[(rh * 4 + b) * G + gA] = fast_sigmoid(vA);   // i/f gates
            UNPACK2(lo, hi, accB[b]);
            float vB = lo + hi + pcB[b];
            sGate[(rh * 4 + b) * G + gB] = fmaf(fast_tanh(vB * taB), s1B, s2B);
        }
        __syncthreads();

        // cell update: rows eb and eb+4
        {
            int r = eb;
            float iv = sGate[r * G + ej];
            float fv = sGate[r * G + 64 + ej];
            float gv = sGate[r * G + 128 + ej];
            float ov = sGate[r * G + 192 + ej];
            c0 = fmaf(fv, c0, iv * gv);
            float h = ov * fast_tanh(c0);
            sH[r * 64 + ej] = h;
            if (WRITE_ALL) {
                __stcs(&hout[(size_t)(b0 + r) * T * HD + (size_t)t * HD + ej], h);
            } else if (t == T - 1) {
                hout[(b0 + r) * HD + ej] = h;
            }
        }
        {
            int r = eb + 4;
            float iv = sGate[r * G + ej];
            float fv = sGate[r * G + 64 + ej];
            float gv = sGate[r * G + 128 + ej];
            float ov = sGate[r * G + 192 + ej];
            c1 = fmaf(fv, c1, iv * gv);
            float h = ov * fast_tanh(c1);
            sH[r * 64 + ej] = h;
            if (WRITE_ALL) {
                __stcs(&hout[(size_t)(b0 + r) * T * HD + (size_t)t * HD + ej], h);
            } else if (t == T - 1) {
                hout[(b0 + r) * HD + ej] = h;
            }
        }
        __syncthreads();

        #pragma unroll
        for (int b = 0; b < 4; b++) { pcA[b] = pnA[b]; pcB[b] = pnB[b]; }
    }
}

// ---------------------------------------------------------------------------
// Decoder v2 (R8, unchanged): BT=4, 256 thr, 2 CTAs/SM.
// ---------------------------------------------------------------------------
__global__ void __launch_bounds__(256, 2) lstm_decoder(
    const float* __restrict__ Wih0, const float* __restrict__ bih0, const float* __restrict__ bhh0,
    const float* __restrict__ Wih1, const float* __restrict__ bih1, const float* __restrict__ bhh1,
    const float* __restrict__ Wfc,  const float* __restrict__ bfc,
    const float* __restrict__ h2last,
    float* __restrict__ out)   // [BATCH, PRED, 64]
{
    extern __shared__ __align__(16) char dyn[];
    ull*   sW1p  = (ull*)dyn;                      // [32][256] ull (64 KB)
    ull*   sWfcp = sW1p + 32 * 256;                // [32][64]  ull (16 KB)
    float* sB1   = (float*)(sWfcp + 32 * 64);      // [256]
    float* sBfc  = sB1 + 256;                      // [64]
    float* sIn   = sBfc + 64;                      // [4][64]
    float* sHm   = sIn + 4 * 64;                   // [4][64]
    float* sGate = sHm + 4 * 64;                   // [4][256]

    const int tid = threadIdx.x;
    const int b0  = blockIdx.x * 4;
    const int g   = tid;
    const int gt  = g >> 6;
    const int eb  = tid >> 6;            // 0..3
    const int ej  = tid & 63;

    ull wa[32];
    {
        const ull* w0 = (const ull*)(Wih0 + g * 64);
        #pragma unroll
        for (int i = 0; i < 32; i++) wa[i] = w0[i];
    }
    const float bias0 = bih0[g] + bhh0[g];
    const float ta = (gt == 2) ? 1.0f : 0.5f;
    const float s1 = (gt == 2) ? 1.0f : 0.5f;
    const float s2 = (gt == 2) ? 0.0f : 0.5f;

    {
        const ull* w1 = (const ull*)(Wih1 + tid * 64);
        #pragma unroll
        for (int i = 0; i < 32; i++) sW1p[i * 256 + tid] = w1[i];
        sB1[tid] = bih1[tid] + bhh1[tid];
        if (tid < 64) {
            const ull* wf = (const ull*)(Wfc + tid * 64);
            #pragma unroll
            for (int i = 0; i < 32; i++) sWfcp[i * 64 + tid] = wf[i];
            sBfc[tid] = bfc[tid];
        }
    }
    sIn[tid] = h2last[b0 * 64 + tid];
    __syncthreads();

    for (int s = 0; s < PRED; s++) {
        // ---- cell0 (weights in regs), src = sIn ----
        {
            ull acc[4];
            #pragma unroll
            for (int b = 0; b < 4; b++) acc[b] = 0ull;
            #pragma unroll
            for (int kg = 0; kg < 16; kg++) {
                ull w01 = wa[2 * kg], w23 = wa[2 * kg + 1];
                #pragma unroll
                for (int b = 0; b < 4; b++) {
                    ulonglong2 xv = *(const ulonglong2*)&sIn[b * 64 + kg * 4];
                    FMA2(acc[b], w01, xv.x);
                    FMA2(acc[b], w23, xv.y);
                }
            }
            #pragma unroll
            for (int b = 0; b < 4; b++) {
                float lo, hi;
                UNPACK2(lo, hi, acc[b]);
                float v = lo + hi + bias0;
                sGate[b * G + g] = fmaf(fast_tanh(v * ta), s1, s2);
            }
            __syncthreads();
            float iv = sGate[eb * G + ej];
            float gv = sGate[eb * G + 128 + ej];
            float ov = sGate[eb * G + 192 + ej];
            sHm[tid] = ov * fast_tanh(iv * gv);
            __syncthreads();
        }
        // ---- cell1 (weights from packed smem), src = sHm ----
        {
            ull acc[4];
            #pragma unroll
            for (int b = 0; b < 4; b++) acc[b] = 0ull;
            #pragma unroll
            for (int kg = 0; kg < 16; kg++) {
                ull w01 = sW1p[(2 * kg) * 256 + g];
                ull w23 = sW1p[(2 * kg + 1) * 256 + g];
                #pragma unroll
                for (int b = 0; b < 4; b++) {
                    ulonglong2 xv = *(const ulonglong2*)&sHm[b * 64 + kg * 4];
                    FMA2(acc[b], w01, xv.x);
                    FMA2(acc[b], w23, xv.y);
                }
            }
            float bias1 = sB1[g];
            #pragma unroll
            for (int b = 0; b < 4; b++) {
                float lo, hi;
                UNPACK2(lo, hi, acc[b]);
                float v = lo + hi + bias1;
                sGate[b * G + g] = fmaf(fast_tanh(v * ta), s1, s2);
            }
            __syncthreads();
            float iv = sGate[eb * G + ej];
            float gv = sGate[eb * G + 128 + ej];
            float ov = sGate[eb * G + 192 + ej];
            sHm[tid] = ov * fast_tanh(iv * gv);
            __syncthreads();
        }
        // ---- FC: one output per thread (eb, ej) ----
        {
            ull acc = 0ull;
            #pragma unroll
            for (int i = 0; i < 16; i++) {
                ull w01 = sWfcp[(2 * i) * 64 + ej];
                ull w23 = sWfcp[(2 * i + 1) * 64 + ej];
                ulonglong2 xv = *(const ulonglong2*)&sHm[eb * 64 + i * 4];
                FMA2(acc, w01, xv.x);
                FMA2(acc, w23, xv.y);
            }
            float lo, hi;
            UNPACK2(lo, hi, acc);
            float pred = lo + hi + sBfc[ej];
            out[(size_t)(b0 + eb) * PRED * HD + (size_t)s * HD + ej] = pred;
            sIn[tid] = pred;
            __syncthreads();
        }
    }
}

// ---------------------------------------------------------------------------
extern "C" void kernel_launch(void* const* d_in, const int* in_sizes, int n_in,
                              void* d_out, int out_size)
{
    const float* x    = (const float*)d_in[0];
    const float* Wih0 = (const float*)d_in[1];
    const float* Whh0 = (const float*)d_in[2];
    const float* bih0 = (const float*)d_in[3];
    const float* bhh0 = (const float*)d_in[4];
    const float* Wih1 = (const float*)d_in[5];
    const float* Whh1 = (const float*)d_in[6];
    const float* bih1 = (const float*)d_in[7];
    const float* bhh1 = (const float*)d_in[8];
    const float* Wfc  = (const float*)d_in[9];
    const float* bfc  = (const float*)d_in[10];
    float* out = (float*)d_out;

    float *pbuf = nullptr, *h1 = nullptr, *h2l = nullptr;
    cudaGetSymbolAddress((void**)&pbuf, g_p);
    cudaGetSymbolAddress((void**)&h1,   g_h1);
    cudaGetSymbolAddress((void**)&h2l,  g_h2last);

    const size_t smDec = (32 * 256 + 32 * 64) * sizeof(ull)
                       + (256 + 64 + 4 * 64 * 2 + 4 * G) * sizeof(float);
    cudaFuncSetAttribute(lstm_decoder, cudaFuncAttributeMaxDynamicSharedMemorySize, (int)smDec);

    input_gemm<<<296, 256>>>(x, Wih0, bih0, bhh0, pbuf, NROWS);
    lstm_recur<true ><<<128, 256>>>(pbuf, Whh0, h1);

    input_gemm<<<296, 256>>>(h1, Wih1, bih1, bhh1, pbuf, NROWS);
    lstm_recur<false><<<128, 256>>>(pbuf, Whh1, h2l);

    lstm_decoder<<<256, 256, smDec>>>(Wih0, bih0, bhh0, Wih1, bih1, bhh1,
                                      Wfc, bfc, h2l, out);
}

// round 10
// speedup vs baseline: 1.1844x; 1.1844x over previous
#include <cuda_runtime.h>

#define BATCH 1024
#define T     336
#define PRED  96
#define D     64
#define HD    64
#define G     256
#define NROWS (BATCH * T)

typedef unsigned long long ull;

// Scratch (device globals: allocation-free per harness rules)
__device__ float g_p[(size_t)BATCH * T * G];       // gate pre-acts (352 MB)
__device__ float g_h1[(size_t)BATCH * T * HD];     // layer-0 hidden states (88 MB)
__device__ float g_h2last[BATCH * HD];

// Packed fp32x2 FMA (Blackwell — PTX-only)
#define FMA2(acc, a, b) \
    asm("fma.rn.f32x2 %0, %1, %2, %0;" : "+l"(acc) : "l"(a), "l"(b))
#define UNPACK2(lo, hi, v) \
    asm("mov.b64 {%0, %1}, %2;" : "=f"(lo), "=f"(hi) : "l"(v))

// HW tanh unit: 1 MUFU
__device__ __forceinline__ float fast_tanh(float x) {
    float y;
    asm("tanh.approx.f32 %0, %1;" : "=f"(y) : "f"(x));
    return y;
}
__device__ __forceinline__ float fast_sigmoid(float x) {
    return fmaf(fast_tanh(0.5f * x), 0.5f, 0.5f);
}

// ---------------------------------------------------------------------------
// Input GEMM v3 (persistent, 256 thr, 1 CTA/SM): 2 gates/thread, 32-row tiles.
// Each broadcast LDS.128 feeds 4 FMA2 (gate-pair reuse) -> FMA-bound.
// thread = (pair = tid&127 -> gates pair & pair+128, rh = tid>>7 -> rows
// [rh*16, rh*16+16) of the 32-row tile).
// ---------------------------------------------------------------------------
__global__ void __launch_bounds__(256, 1) input_gemm(
    const float* __restrict__ In,   // [N, 64]
    const float* __restrict__ W,    // [256, 64]
    const float* __restrict__ b1,
    const float* __restrict__ b2,
    float* __restrict__ P,          // [N, 256]
    int N)
{
    __shared__ __align__(16) float sX[2][32 * 64];

    const int tid  = threadIdx.x;
    const int pair = tid & 127;
    const int rh   = tid >> 7;          // 0/1
    const int gA   = pair;
    const int gB   = pair + 128;

    ull wA[32], wB[32];
    {
        const ull* wa = (const ull*)(W + gA * 64);
        const ull* wb = (const ull*)(W + gB * 64);
        #pragma unroll
        for (int i = 0; i < 32; i++) { wA[i] = wa[i]; wB[i] = wb[i]; }
    }
    const float biasA = b1[gA] + b2[gA];
    const float biasB = b1[gB] + b2[gB];

    const int ntiles = N / 32;          // 10752
    const int stride = gridDim.x;
    int tile = blockIdx.x;
    if (tile >= ntiles) return;

    // Each thread loads 8 floats (2 float4) of the 32x64 tile
    float4 xr0 = *(const float4*)(In + (size_t)tile * (32 * 64) + tid * 8);
    float4 xr1 = *(const float4*)(In + (size_t)tile * (32 * 64) + tid * 8 + 4);
    *(float4*)&sX[0][tid * 8]     = xr0;
    *(float4*)&sX[0][tid * 8 + 4] = xr1;
    __syncthreads();

    int buf = 0;
    for (; tile < ntiles; tile += stride) {
        const int nxt = tile + stride;
        if (nxt < ntiles) {
            xr0 = *(const float4*)(In + (size_t)nxt * (32 * 64) + tid * 8);
            xr1 = *(const float4*)(In + (size_t)nxt * (32 * 64) + tid * 8 + 4);
        }

        ull accA[16], accB[16];
        #pragma unroll
        for (int r = 0; r < 16; r++) { accA[r] = 0ull; accB[r] = 0ull; }

        const float* xb = sX[buf] + rh * (16 * 64);
        #pragma unroll
        for (int kg = 0; kg < 16; kg++) {
            ull a01 = wA[2 * kg], a23 = wA[2 * kg + 1];
            ull b01 = wB[2 * kg], b23 = wB[2 * kg + 1];
            #pragma unroll
            for (int r = 0; r < 16; r++) {
                ulonglong2 xv = *(const ulonglong2*)&xb[r * 64 + kg * 4];
                FMA2(accA[r], a01, xv.x);
                FMA2(accA[r], a23, xv.y);
                FMA2(accB[r], b01, xv.x);
                FMA2(accB[r], b23, xv.y);
            }
        }

        if (nxt < ntiles) {
            *(float4*)&sX[buf ^ 1][tid * 8]     = xr0;
            *(float4*)&sX[buf ^ 1][tid * 8 + 4] = xr1;
        }

        float* prow = P + ((size_t)tile * 32 + rh * 16) * G;
        #pragma unroll
        for (int r = 0; r < 16; r++) {
            float lo, hi;
            UNPACK2(lo, hi, accA[r]);
            __stcs(&prow[(size_t)r * G + gA], lo + hi + biasA);
            UNPACK2(lo, hi, accB[r]);
            __stcs(&prow[(size_t)r * G + gB], lo + hi + biasB);
        }
        __syncthreads();
        buf ^= 1;
    }
}

// ---------------------------------------------------------------------------
// Recurrent scan (R8 / R5 version — known good 425us): BT=4, 256 thr,
// 2 CTAs/SM, smem gate exchange, 2 barriers/step, c in register.
// ---------------------------------------------------------------------------
template <bool WRITE_ALL>
__global__ void __launch_bounds__(256, 2) lstm_recur(
    const float* __restrict__ P,     // [BATCH, T, 256] (biases included)
    const float* __restrict__ Whh,   // [256, 64]
    float* __restrict__ hout)        // WRITE_ALL ? [BATCH,T,64] : [BATCH,64]
{
    __shared__ __align__(16) float sH[4 * 64];
    __shared__ __align__(16) float sGate[4 * G];

    const int tid = threadIdx.x;
    const int b0  = blockIdx.x * 4;
    const int g   = tid;
    const int gt  = g >> 6;              // warp-uniform

    ull w[32];
    {
        const ull* wp = (const ull*)(Whh + g * 64);
        #pragma unroll
        for (int i = 0; i < 32; i++) w[i] = wp[i];
    }

    const int eb = tid >> 6;             // 0..3
    const int ej = tid & 63;
    float c = 0.0f;

    sH[tid] = 0.0f;

    const float* pbase = P + ((size_t)b0 * T) * G + g;
    float pc[4];
    #pragma unroll
    for (int b = 0; b < 4; b++) pc[b] = pbase[(size_t)b * T * G];
    __syncthreads();

    for (int t = 0; t < T; t++) {
        float pn[4];
        if (t + 1 < T) {
            #pragma unroll
            for (int b = 0; b < 4; b++)
                pn[b] = __ldcs(&pbase[(size_t)b * T * G + (size_t)(t + 1) * G]);
        }

        ull acc[4];
        #pragma unroll
        for (int b = 0; b < 4; b++) acc[b] = 0ull;

        #pragma unroll
        for (int kg = 0; kg < 16; kg++) {
            ull w01 = w[2 * kg], w23 = w[2 * kg + 1];
            #pragma unroll
            for (int b = 0; b < 4; b++) {
                ulonglong2 hv = *(const ulonglong2*)&sH[b * 64 + kg * 4];
                FMA2(acc[b], w01, hv.x);
                FMA2(acc[b], w23, hv.y);
            }
        }

        #pragma unroll
        for (int b = 0; b < 4; b++) {
            float lo, hi;
            UNPACK2(lo, hi, acc[b]);
            float v = lo + hi + pc[b];
            sGate[b * G + g] = (gt == 2) ? fast_tanh(v) : fast_sigmoid(v);
        }
        __syncthreads();

        {
            float iv = sGate[eb * G + ej];
            float fv = sGate[eb * G + 64 + ej];
            float gv = sGate[eb * G + 128 + ej];
            float ov = sGate[eb * G + 192 + ej];
            c = fmaf(fv, c, iv * gv);
            float h = ov * fast_tanh(c);
            sH[tid] = h;
            if (WRITE_ALL) {
                __stcs(&hout[(size_t)(b0 + eb) * T * HD + (size_t)t * HD + ej], h);
            } else if (t == T - 1) {
                hout[(b0 + eb) * HD + ej] = h;
            }
        }
        __syncthreads();

        #pragma unroll
        for (int b = 0; b < 4; b++) pc[b] = pn[b];
    }
}

// ---------------------------------------------------------------------------
// Decoder v2 (R8, unchanged): BT=4, 256 thr, 2 CTAs/SM.
// ---------------------------------------------------------------------------
__global__ void __launch_bounds__(256, 2) lstm_decoder(
    const float* __restrict__ Wih0, const float* __restrict__ bih0, const float* __restrict__ bhh0,
    const float* __restrict__ Wih1, const float* __restrict__ bih1, const float* __restrict__ bhh1,
    const float* __restrict__ Wfc,  const float* __restrict__ bfc,
    const float* __restrict__ h2last,
    float* __restrict__ out)   // [BATCH, PRED, 64]
{
    extern __shared__ __align__(16) char dyn[];
    ull*   sW1p  = (ull*)dyn;                      // [32][256] ull (64 KB)
    ull*   sWfcp = sW1p + 32 * 256;                // [32][64]  ull (16 KB)
    float* sB1   = (float*)(sWfcp + 32 * 64);      // [256]
    float* sBfc  = sB1 + 256;                      // [64]
    float* sIn   = sBfc + 64;                      // [4][64]
    float* sHm   = sIn + 4 * 64;                   // [4][64]
    float* sGate = sHm + 4 * 64;                   // [4][256]

    const int tid = threadIdx.x;
    const int b0  = blockIdx.x * 4;
    const int g   = tid;
    const int gt  = g >> 6;
    const int eb  = tid >> 6;            // 0..3
    const int ej  = tid & 63;

    ull wa[32];
    {
        const ull* w0 = (const ull*)(Wih0 + g * 64);
        #pragma unroll
        for (int i = 0; i < 32; i++) wa[i] = w0[i];
    }
    const float bias0 = bih0[g] + bhh0[g];
    const float ta = (gt == 2) ? 1.0f : 0.5f;
    const float s1 = (gt == 2) ? 1.0f : 0.5f;
    const float s2 = (gt == 2) ? 0.0f : 0.5f;

    {
        const ull* w1 = (const ull*)(Wih1 + tid * 64);
        #pragma unroll
        for (int i = 0; i < 32; i++) sW1p[i * 256 + tid] = w1[i];
        sB1[tid] = bih1[tid] + bhh1[tid];
        if (tid < 64) {
            const ull* wf = (const ull*)(Wfc + tid * 64);
            #pragma unroll
            for (int i = 0; i < 32; i++) sWfcp[i * 64 + tid] = wf[i];
            sBfc[tid] = bfc[tid];
        }
    }
    sIn[tid] = h2last[b0 * 64 + tid];
    __syncthreads();

    for (int s = 0; s < PRED; s++) {
        // ---- cell0 (weights in regs), src = sIn ----
        {
            ull acc[4];
            #pragma unroll
            for (int b = 0; b < 4; b++) acc[b] = 0ull;
            #pragma unroll
            for (int kg = 0; kg < 16; kg++) {
                ull w01 = wa[2 * kg], w23 = wa[2 * kg + 1];
                #pragma unroll
                for (int b = 0; b < 4; b++) {
                    ulonglong2 xv = *(const ulonglong2*)&sIn[b * 64 + kg * 4];
                    FMA2(acc[b], w01, xv.x);
                    FMA2(acc[b], w23, xv.y);
                }
            }
            #pragma unroll
            for (int b = 0; b < 4; b++) {
                float lo, hi;
                UNPACK2(lo, hi, acc[b]);
                float v = lo + hi + bias0;
                sGate[b * G + g] = fmaf(fast_tanh(v * ta), s1, s2);
            }
            __syncthreads();
            float iv = sGate[eb * G + ej];
            float gv = sGate[eb * G + 128 + ej];
            float ov = sGate[eb * G + 192 + ej];
            sHm[tid] = ov * fast_tanh(iv * gv);
            __syncthreads();
        }
        // ---- cell1 (weights from packed smem), src = sHm ----
        {
            ull acc[4];
            #pragma unroll
            for (int b = 0; b < 4; b++) acc[b] = 0ull;
            #pragma unroll
            for (int kg = 0; kg < 16; kg++) {
                ull w01 = sW1p[(2 * kg) * 256 + g];
                ull w23 = sW1p[(2 * kg + 1) * 256 + g];
                #pragma unroll
                for (int b = 0; b < 4; b++) {
                    ulonglong2 xv = *(const ulonglong2*)&sHm[b * 64 + kg * 4];
                    FMA2(acc[b], w01, xv.x);
                    FMA2(acc[b], w23, xv.y);
                }
            }
            float bias1 = sB1[g];
            #pragma unroll
            for (int b = 0; b < 4; b++) {
                float lo, hi;
                UNPACK2(lo, hi, acc[b]);
                float v = lo + hi + bias1;
                sGate[b * G + g] = fmaf(fast_tanh(v * ta), s1, s2);
            }
            __syncthreads();
            float iv = sGate[eb * G + ej];
            float gv = sGate[eb * G + 128 + ej];
            float ov = sGate[eb * G + 192 + ej];
            sHm[tid] = ov * fast_tanh(iv * gv);
            __syncthreads();
        }
        // ---- FC: one output per thread (eb, ej) ----
        {
            ull acc = 0ull;
            #pragma unroll
            for (int i = 0; i < 16; i++) {
                ull w01 = sWfcp[(2 * i) * 64 + ej];
                ull w23 = sWfcp[(2 * i + 1) * 64 + ej];
                ulonglong2 xv = *(const ulonglong2*)&sHm[eb * 64 + i * 4];
                FMA2(acc, w01, xv.x);
                FMA2(acc, w23, xv.y);
            }
            float lo, hi;
            UNPACK2(lo, hi, acc);
            float pred = lo + hi + sBfc[ej];
            out[(size_t)(b0 + eb) * PRED * HD + (size_t)s * HD + ej] = pred;
            sIn[tid] = pred;
            __syncthreads();
        }
    }
}

// ---------------------------------------------------------------------------
extern "C" void kernel_launch(void* const* d_in, const int* in_sizes, int n_in,
                              void* d_out, int out_size)
{
    const float* x    = (const float*)d_in[0];
    const float* Wih0 = (const float*)d_in[1];
    const float* Whh0 = (const float*)d_in[2];
    const float* bih0 = (const float*)d_in[3];
    const float* bhh0 = (const float*)d_in[4];
    const float* Wih1 = (const float*)d_in[5];
    const float* Whh1 = (const float*)d_in[6];
    const float* bih1 = (const float*)d_in[7];
    const float* bhh1 = (const float*)d_in[8];
    const float* Wfc  = (const float*)d_in[9];
    const float* bfc  = (const float*)d_in[10];
    float* out = (float*)d_out;

    float *pbuf = nullptr, *h1 = nullptr, *h2l = nullptr;
    cudaGetSymbolAddress((void**)&pbuf, g_p);
    cudaGetSymbolAddress((void**)&h1,   g_h1);
    cudaGetSymbolAddress((void**)&h2l,  g_h2last);

    const size_t smDec = (32 * 256 + 32 * 64) * sizeof(ull)
                       + (256 + 64 + 4 * 64 * 2 + 4 * G) * sizeof(float);
    cudaFuncSetAttribute(lstm_decoder, cudaFuncAttributeMaxDynamicSharedMemorySize, (int)smDec);

    input_gemm<<<148, 256>>>(x, Wih0, bih0, bhh0, pbuf, NROWS);
    lstm_recur<true ><<<256, 256>>>(pbuf, Whh0, h1);

    input_gemm<<<148, 256>>>(h1, Wih1, bih1, bhh1, pbuf, NROWS);
    lstm_recur<false><<<256, 256>>>(pbuf, Whh1, h2l);

    lstm_decoder<<<256, 256, smDec>>>(Wih0, bih0, bhh0, Wih1, bih1, bhh1,
                                      Wfc, bfc, h2l, out);
}